// round 6
// baseline (speedup 1.0000x reference)
#include <cuda_runtime.h>

// ---------------------------------------------------------------------------
// DifferentiablePhysicsEngine energy on GB300 — single fused kernel, R3 retry.
// LJ retile: i-tiles of 256 rows (2 rows/thread), j-tiles of 128.
//   per batch: 16 diag-half blocks (full square, self-subtract, weight 1)
//            + 56 off-diag blocks (weight 2)            -> 72 blocks
//   [0,576)      LJ
//   [576,704)    HB N-vs-O, 8 batches x 4 i-tiles x 4 j-chunks
//   [704,712)    per-batch stats
// Last-arriving block does the fixed-order final combine in float.
// ---------------------------------------------------------------------------

static constexpr int Bsz  = 8;
static constexpr int Ssz  = 512;
static constexpr int NF   = Ssz * 4;            // 2048 flat atoms
static constexpr int TPB  = 128;
static constexpr int JT   = 128;                // j tile
static constexpr int LJ_PER_B   = 72;           // 16 diag-half + 56 off-diag
static constexpr int LJ_BLOCKS  = Bsz * LJ_PER_B;     // 576
static constexpr int HB_IT = 4, HB_JC = 4;
static constexpr int HB_BLOCKS  = Bsz * HB_IT * HB_JC; // 128
static constexpr int STAT_BLOCKS = Bsz;                // 8
static constexpr int TOTAL_BLOCKS = LJ_BLOCKS + HB_BLOCKS + STAT_BLOCKS; // 712

__device__ float g_lj[LJ_BLOCKS];
__device__ float g_hb[HB_BLOCKS];
__device__ float g_stats[Bsz][8];
__device__ unsigned int g_count = 0;

typedef unsigned long long u64;

__device__ __forceinline__ u64 pk2(float lo, float hi) {
    u64 r; asm("mov.b64 %0, {%1,%2};" : "=l"(r) : "f"(lo), "f"(hi)); return r;
}
__device__ __forceinline__ void unpk2(u64 p, float& lo, float& hi) {
    asm("mov.b64 {%0,%1}, %2;" : "=f"(lo), "=f"(hi) : "l"(p));
}
__device__ __forceinline__ u64 addx2(u64 a, u64 b) {
    u64 d; asm("add.rn.f32x2 %0, %1, %2;" : "=l"(d) : "l"(a), "l"(b)); return d;
}
__device__ __forceinline__ u64 mulx2(u64 a, u64 b) {
    u64 d; asm("mul.rn.f32x2 %0, %1, %2;" : "=l"(d) : "l"(a), "l"(b)); return d;
}
__device__ __forceinline__ u64 fmax2(u64 a, u64 b, u64 c) {
    u64 d; asm("fma.rn.f32x2 %0, %1, %2, %3;" : "=l"(d) : "l"(a), "l"(b), "l"(c)); return d;
}
__device__ __forceinline__ float fsqrt_ap(float x) {
    float r; asm("sqrt.approx.f32 %0, %1;" : "=f"(r) : "f"(x)); return r;
}
__device__ __forceinline__ float fex2_ap(float x) {
    float r; asm("ex2.approx.f32 %0, %1;" : "=f"(r) : "f"(x)); return r;
}

static constexpr u64 EPS_P   = 0x358637BD358637BDull; // {1e-6f,1e-6f}
static constexpr u64 NEG1_P  = 0xBF800000BF800000ull; // {-1,-1}
static constexpr u64 THREE_P = 0x4040000040400000ull; // {3,3}

__device__ __forceinline__ float block_reduce(float v, float* red) {
    int t = threadIdx.x;
    red[t] = v;
    __syncthreads();
#pragma unroll
    for (int off = TPB / 2; off > 0; off >>= 1) {
        if (t < off) red[t] += red[t + off];
        __syncthreads();
    }
    float r = red[0];
    __syncthreads();
    return r;
}

// 2 LJ pairs for one i row (packed). nx/ny/nz: negated j coords, mp: masks.
#define LJ2(XIP, YIP, ZIP, nx, ny, nz, mp, acc)                         \
    do {                                                                \
        u64 dX = addx2(XIP, (nx));                                      \
        u64 dY = addx2(YIP, (ny));                                      \
        u64 dZ = addx2(ZIP, (nz));                                      \
        u64 d2 = fmax2(dZ, dZ, EPS_P);                                  \
        d2 = fmax2(dY, dY, d2);                                         \
        d2 = fmax2(dX, dX, d2);                                         \
        float d2a, d2b; unpk2(d2, d2a, d2b);                            \
        float ra = fsqrt_ap(d2a), rb = fsqrt_ap(d2b);                   \
        u64 sv = fmax2(pk2(ra, rb), NEG1_P, THREE_P);                   \
        float sa, sb; unpk2(sv, sa, sb);                                \
        sa = fmaxf(sa, 0.0f); sb = fmaxf(sb, 0.0f);                     \
        u64 ov  = pk2(sa, sb);                                          \
        u64 ov2 = mulx2(ov, ov);                                        \
        u64 ov4 = mulx2(ov2, ov2);                                      \
        acc = fmax2(ov4, (mp), acc);                                    \
    } while (0)

#define HB_PAIR(xj, yj, zj, mj, jg)                                     \
    do {                                                                \
        float dx = xi - (xj), dy = yi - (yj), dz = zi - (zj);           \
        float d2 = fmaf(dx, dx, fmaf(dy, dy, dz * dz));                 \
        float r  = fsqrt_ap(d2);                                        \
        float d  = __fmaf_rn(r, -1.0f, 2.9f);                           \
        float e  = fex2_ap(d * d * (-18.033688011112043f));             \
        int  dj  = (jg) - i;                                            \
        if (dj > 2 || dj < -2) acc = fmaf(e, (mj), acc);                \
    } while (0)

__global__ __launch_bounds__(TPB)
void energy_fused(const float* __restrict__ coords,
                  const float* __restrict__ motors,
                  const float* __restrict__ mask,
                  float* __restrict__ out) {
    __shared__ alignas(16) float smem[4 * JT]; // 2 KB
    __shared__ float red[TPB];
    __shared__ int s_last;
    const int blk = blockIdx.x;
    const int t   = threadIdx.x;

    if (blk < LJ_BLOCKS) {
        // --------------------------- LJ clash ------------------------------
        const int b = blk / LJ_PER_B;
        const int p = blk % LJ_PER_B;
        int ibase, jbase, isDiagHalf, h = 0;
        if (p < 16) {                 // diag-half block
            const int I = p >> 1;  h = p & 1;
            ibase = 256 * I;
            jbase = 256 * I + 128 * h;
            isDiagHalf = 1;
        } else {                      // off-diag block, weight 2
            int q = p - 16, I = 0;
            while (q >= 14 - 2 * I) { q -= 14 - 2 * I; ++I; }
            ibase = 256 * I;
            jbase = 128 * (2 * I + 2 + q);
            isDiagHalf = 0;
        }

        const float* cb = coords + (size_t)b * NF * 3;
        const float* mb = mask + (size_t)b * Ssz;
        float* snx = smem;          float* sny = smem + JT;
        float* snz = smem + 2 * JT; float* sm  = smem + 3 * JT;

        const int jr = jbase + t;
        snx[t] = -cb[jr * 3 + 0];
        sny[t] = -cb[jr * 3 + 1];
        snz[t] = -cb[jr * 3 + 2];
        sm[t]  =  mb[jr >> 2];

        const int ig0 = ibase + t;
        const int ig1 = ibase + 128 + t;
        const float xi0 = cb[ig0 * 3 + 0], yi0 = cb[ig0 * 3 + 1], zi0 = cb[ig0 * 3 + 2];
        const float xi1 = cb[ig1 * 3 + 0], yi1 = cb[ig1 * 3 + 1], zi1 = cb[ig1 * 3 + 2];
        const float mi0 = mb[ig0 >> 2];
        const float mi1 = mb[ig1 >> 2];
        __syncthreads();

        const u64 X0 = pk2(xi0, xi0), Y0 = pk2(yi0, yi0), Z0 = pk2(zi0, zi0);
        const u64 X1 = pk2(xi1, xi1), Y1 = pk2(yi1, yi1), Z1 = pk2(zi1, zi1);
        const ulonglong2* NX = (const ulonglong2*)snx;
        const ulonglong2* NY = (const ulonglong2*)sny;
        const ulonglong2* NZ = (const ulonglong2*)snz;
        const ulonglong2* MM = (const ulonglong2*)sm;
        u64 aA0 = 0ull, aB0 = 0ull, aA1 = 0ull, aB1 = 0ull;
#pragma unroll 8
        for (int g = 0; g < JT / 4; ++g) {
            ulonglong2 X = NX[g], Y = NY[g], Z = NZ[g], M = MM[g];
            LJ2(X0, Y0, Z0, X.x, Y.x, Z.x, M.x, aA0);
            LJ2(X0, Y0, Z0, X.y, Y.y, Z.y, M.y, aB0);
            LJ2(X1, Y1, Z1, X.x, Y.x, Z.x, M.x, aA1);
            LJ2(X1, Y1, Z1, X.y, Y.y, Z.y, M.y, aB1);
        }
        float a0, a1, b0, b1, c0f, c1f, d0, d1;
        unpk2(aA0, a0, a1); unpk2(aB0, b0, b1);
        unpk2(aA1, c0f, c1f); unpk2(aB1, d0, d1);
        float tot0 = (a0 + a1) + (b0 + b1);
        float tot1 = (c0f + c1f) + (d0 + d1);
        float v = tot0 * mi0 + tot1 * mi1;
        if (isDiagHalf) {
            // self term: replicate the loop's exact arithmetic for d2 == EPS
            const float rs = fsqrt_ap(1e-6f);
            const float os = fmaxf(__fmaf_rn(rs, -1.0f, 3.0f), 0.0f);
            const float o2 = os * os;
            const float selfc = o2 * o2;
            const float ms = (h == 0) ? mi0 : mi1;
            v -= selfc * ms * ms;
        }
        float r = block_reduce(v, red);
        if (t == 0) g_lj[blk] = isDiagHalf ? r : 2.0f * r;

    } else if (blk < LJ_BLOCKS + HB_BLOCKS) {
        // --------------------- hydrogen-bond term --------------------------
        const int q  = blk - LJ_BLOCKS;
        const int b  = q / (HB_IT * HB_JC);
        const int rr = q % (HB_IT * HB_JC);
        const int it = rr / HB_JC;
        const int jc = rr % HB_JC;
        const float* cb = coords + (size_t)b * NF * 3;
        const float* mb = mask + (size_t)b * Ssz;
        float* ox = smem;          float* oy = smem + JT;
        float* oz = smem + 2 * JT; float* om = smem + 3 * JT;

        const int j0 = jc * JT;
        {
            const float* row = cb + ((j0 + t) * 4 + 3) * 3; // O atom
            ox[t] = row[0]; oy[t] = row[1]; oz[t] = row[2];
            om[t] = mb[j0 + t];
        }
        const int i = it * JT + t;
        const float* nr = cb + i * 12; // N atom
        const float xi = nr[0], yi = nr[1], zi = nr[2];
        const float mi = mb[i];
        __syncthreads();

        float acc = 0.0f;
        const float4* X4 = (const float4*)ox;
        const float4* Y4 = (const float4*)oy;
        const float4* Z4 = (const float4*)oz;
        const float4* M4 = (const float4*)om;
#pragma unroll 4
        for (int g = 0; g < JT / 4; ++g) {
            float4 x = X4[g], y = Y4[g], z = Z4[g], m = M4[g];
            const int jb = j0 + 4 * g;
            HB_PAIR(x.x, y.x, z.x, m.x, jb + 0);
            HB_PAIR(x.y, y.y, z.y, m.y, jb + 1);
            HB_PAIR(x.z, y.z, z.z, m.z, jb + 2);
            HB_PAIR(x.w, y.w, z.w, m.w, jb + 3);
        }
        float v = block_reduce(acc * mi, red);
        if (t == 0) g_hb[q] = v;

    } else {
        // ------------- per-batch stats -------------------------------------
        const int b = blk - LJ_BLOCKS - HB_BLOCKS;
        const float* cb = coords + (size_t)b * NF * 3;
        const float* mb = mask + (size_t)b * Ssz;
        const float* mo = motors + (size_t)b * Ssz * 8;

        float msum = 0.f, msum2 = 0.f;
        float s1x = 0.f, s1y = 0.f, s1z = 0.f, s2 = 0.f;
        float mot = 0.f, mm = 0.f;

        for (int s = t; s < Ssz; s += TPB) {
            const float m = mb[s];
            msum += m;
            msum2 = fmaf(m, m, msum2);
            const float* ca = cb + (s * 4 + 1) * 3;
            const float cx = ca[0], cy = ca[1], cz = ca[2];
            s1x = fmaf(cx, m, s1x);
            s1y = fmaf(cy, m, s1y);
            s1z = fmaf(cz, m, s1z);
            s2  = fmaf(fmaf(cx, cx, fmaf(cy, cy, cz * cz)), m, s2);
            if (s < Ssz - 1) {
                const float mn = mb[s + 1];
                const float4* r4 = (const float4*)(mo + s * 8);
                float4 a0 = r4[0], a1 = r4[1], b0 = r4[2], b1 = r4[3];
                float d, ds = 0.f;
                d = b0.x - a0.x; ds = fmaf(d, d, ds);
                d = b0.y - a0.y; ds = fmaf(d, d, ds);
                d = b0.z - a0.z; ds = fmaf(d, d, ds);
                d = b0.w - a0.w; ds = fmaf(d, d, ds);
                d = b1.x - a1.x; ds = fmaf(d, d, ds);
                d = b1.y - a1.y; ds = fmaf(d, d, ds);
                d = b1.z - a1.z; ds = fmaf(d, d, ds);
                d = b1.w - a1.w; ds = fmaf(d, d, ds);
                mot = fmaf(ds, m * mn, mot);
                mm  = fmaf(m, mn, mm);
            }
        }
        float vals[8] = {msum, msum2, s1x, s1y, s1z, s2, mot, mm};
#pragma unroll
        for (int k = 0; k < 8; ++k) {
            float v = block_reduce(vals[k], red);
            if (t == 0) g_stats[b][k] = v;
        }
    }

    // ------------------- last-block final combine (fixed order) ------------
    __syncthreads();
    if (t == 0) {
        __threadfence();
        unsigned int old = atomicAdd(&g_count, 1u);
        s_last = (old == (unsigned int)(TOTAL_BLOCKS - 1)) ? 1 : 0;
    }
    __syncthreads();
    if (!s_last) return;

    __threadfence();
    float a = 0.f;
    for (int idx = t; idx < LJ_BLOCKS; idx += TPB) a += __ldcg(&g_lj[idx]);
    const float S_lj = block_reduce(a, red);

    float h2 = (t < HB_BLOCKS) ? __ldcg(&g_hb[t]) : 0.f;
    const float S_hb = block_reduce(h2, red);

    if (t == 0) {
        float P = 0.f, Mtot = 0.f, Smot = 0.f, Smm = 0.f, rg = 0.f;
#pragma unroll
        for (int b = 0; b < Bsz; ++b) {
            float st[8];
#pragma unroll
            for (int k = 0; k < 8; ++k) st[k] = __ldcg(&g_stats[b][k]);
            const float ms = st[0], ms2 = st[1];
            P    = fmaf(16.f * ms, ms, P) - 4.f * ms2;
            Mtot += ms;
            Smot += st[6];
            Smm  += st[7];
            const float den = ms + 1e-6f;
            const float inv = __fdividef(1.0f, den);
            const float ux = st[2] * inv, uy = st[3] * inv, uz = st[4] * inv;
            const float dot = ux * st[2] + uy * st[3] + uz * st[4];
            const float u2  = ux * ux + uy * uy + uz * uz;
            rg += (st[5] - 2.f * dot + u2 * ms) * inv;
        }
        rg *= (1.0f / (float)Bsz);
        const float lj    = S_lj * __fdividef(1.0f, P + 1e-6f);
        const float hb    = -S_hb * __fdividef(1.0f, Mtot + 1e-6f);
        const float motor = Smot * __fdividef(1.0f, Smm + 1e-6f);
        out[0] = lj + 0.5f * hb + 0.1f * motor + 0.05f * rg;
        g_count = 0; // reset for next graph replay
    }
}

extern "C" void kernel_launch(void* const* d_in, const int* in_sizes, int n_in,
                              void* d_out, int out_size) {
    const float* coords = nullptr;
    const float* motors = nullptr;
    const float* mask   = nullptr;
    for (int i = 0; i < n_in; ++i) {
        if (in_sizes[i] == Bsz * Ssz * 4 * 3)   coords = (const float*)d_in[i];
        else if (in_sizes[i] == Bsz * Ssz * 8)  motors = (const float*)d_in[i];
        else if (in_sizes[i] == Bsz * Ssz)      mask   = (const float*)d_in[i];
    }
    energy_fused<<<TOTAL_BLOCKS, TPB>>>(coords, motors, mask, (float*)d_out);
}